// round 2
// baseline (speedup 1.0000x reference)
#include <cuda_runtime.h>
#include <math.h>

// Problem constants (fixed by the benchmark)
#define NN   4096   // nodes
#define EE   4096   // edges
#define BB   128    // graphs
#define DD   256    // hidden dim
#define INF  74     // input feature dim
#define EHH  512    // edge-net hidden

// ---------------- scratch (static device globals; no allocation) ----------------
#define OFF_AGG1  0ULL                                  // NN*INF
#define OFF_AGG2  (OFF_AGG1 + (size_t)NN*INF)           // NN*DD
#define OFF_MACC  (OFF_AGG2 + (size_t)NN*DD)            // NN*DD
#define OFF_NSUM  (OFF_MACC + (size_t)NN*DD)            // BB*DD
#define OFF_ESUM  (OFF_NSUM + (size_t)BB*DD)            // BB
#define ZERO_F    (OFF_ESUM + (size_t)BB)

#define OFF_INVS  ZERO_F                                // NN
#define OFF_INVD  (OFF_INVS + (size_t)NN)               // NN
#define OFF_U     (OFF_INVD + (size_t)NN)               // EHH
#define OFF_W     (OFF_U + (size_t)EHH)                 // EHH
#define OFF_BCAT  (OFF_W + (size_t)EHH)                 // DD*512
#define OFF_H1    (OFF_BCAT + (size_t)DD*512)           // NN*DD
#define OFF_H2    (OFF_H1 + (size_t)NN*DD)              // NN*DD
#define OFF_H     (OFF_H2 + (size_t)NN*DD)              // NN*DD
#define OFF_HMC   (OFF_H + (size_t)NN*DD)               // NN*512
#define OFF_M     (OFF_HMC + (size_t)NN*512)            // NN*DD
#define OFF_GI    (OFF_M + (size_t)NN*DD)               // NN*768
#define OFF_GH    (OFF_GI + (size_t)NN*768)             // NN*768
#define OFF_HN    (OFF_GH + (size_t)NN*768)             // NN*DD
#define OFF_GHF   (OFF_HN + (size_t)NN*DD)              // BB*257
#define TOT_F     (OFF_GHF + (size_t)BB*257)

__device__ float g_scratch[TOT_F];

#define IOFF_DEGOUT 0
#define IOFF_DEGIN  NN
#define IOFF_NCNT   (2*NN)
#define IOFF_ECNT   (2*NN + BB)
#define TOT_I       (2*NN + 2*BB)
__device__ int g_iscratch[TOT_I];

// ---------------- kernels ----------------

__global__ void k_zero() {
    size_t i = (size_t)blockIdx.x * blockDim.x + threadIdx.x;
    if (i < ZERO_F) g_scratch[i] = 0.f;
    if (i < TOT_I) g_iscratch[i] = 0;
}

__global__ void k_prep(const int* __restrict__ src, const int* __restrict__ dst,
                       const int* __restrict__ node_gid, const int* __restrict__ edge_gid,
                       const float* __restrict__ edge_type) {
    int i = blockIdx.x * blockDim.x + threadIdx.x;
    if (i < EE) {
        atomicAdd(&g_iscratch[IOFF_DEGOUT + src[i]], 1);
        atomicAdd(&g_iscratch[IOFF_DEGIN + dst[i]], 1);
        atomicAdd(&g_iscratch[IOFF_ECNT + edge_gid[i]], 1);
        atomicAdd(&g_scratch[OFF_ESUM + edge_gid[i]], edge_type[i]);
    }
    if (i < NN) {
        atomicAdd(&g_iscratch[IOFF_NCNT + node_gid[i]], 1);
    }
}

__global__ void k_finalize(const float* __restrict__ We1, const float* __restrict__ be1) {
    int i = blockIdx.x * blockDim.x + threadIdx.x;
    if (i < NN) {
        float od = (float)max(g_iscratch[IOFF_DEGOUT + i], 1);
        float id = (float)max(g_iscratch[IOFF_DEGIN + i], 1);
        g_scratch[OFF_INVS + i] = rsqrtf(od);
        g_scratch[OFF_INVD + i] = rsqrtf(id);
    }
    if (i < EHH) {
        float a = We1[i], b = be1[i];
        float s = (a * 0.5f + b >= 0.f) ? 1.f : 0.01f;
        g_scratch[OFF_U + i] = s * a;
        g_scratch[OFF_W + i] = s * b;
    }
}

// gconv1 scatter: agg1[dst] += node_feats[src] * inv_s[src]
__global__ void k_scatter1(const float* __restrict__ x, const int* __restrict__ src,
                           const int* __restrict__ dst) {
    int t = blockIdx.x * blockDim.x + threadIdx.x;
    if (t >= EE * INF) return;
    int e = t / INF, j = t - e * INF;
    int s = src[e], d = dst[e];
    atomicAdd(&g_scratch[OFF_AGG1 + (size_t)d * INF + j],
              x[(size_t)s * INF + j] * g_scratch[OFF_INVS + s]);
}

// Build Bcat[d][0:256]=M and Bcat[d][256:512]=C2 (streams We2 once)
__global__ void k_build_bcat(const float* __restrict__ We2, const float* __restrict__ be2) {
    __shared__ float su_s[EHH], sw_s[EHH];
    for (int i = threadIdx.x; i < EHH; i += blockDim.x) {
        su_s[i] = g_scratch[OFF_U + i];
        sw_s[i] = g_scratch[OFF_W + i];
    }
    __syncthreads();
    int j = blockIdx.x * blockDim.x + threadIdx.x;  // 0..65535  (d*256+f)
    if (j >= DD * DD) return;
    float su = 0.f, sw = 0.f;
    #pragma unroll 8
    for (int k = 0; k < EHH; k++) {
        float v = We2[(size_t)k * (DD * DD) + j];
        su += su_s[k] * v;
        sw += sw_s[k] * v;
    }
    int d = j >> 8, f = j & 255;
    g_scratch[OFF_BCAT + (size_t)d * 512 + f] = su;
    g_scratch[OFF_BCAT + (size_t)d * 512 + 256 + f] = sw + be2[j];
}

// -------- fp32x2 (FFMA2) GEMM: C = act(rowscale[m]*(A@B) + bias[n]) --------
// Tile 64x64x16, 128 threads, per-thread 8x4, accumulators packed over M-row pairs.
// A: [M,K] row-major.  B: [K,N] row-major (TRANSB=false) or [N,K] row-major (TRANSB=true).
template<bool TRANSB, int ACT>  // ACT: 0 none, 1 relu, 2 leaky(0.01)
__global__ void __launch_bounds__(128)
k_gemm2(const float* __restrict__ A, const float* __restrict__ Bm,
        float* __restrict__ C, int M, int Nd, int K,
        const float* __restrict__ bias, const float* __restrict__ rowscale) {
    __shared__ float As[16][64];   // [k][m]
    __shared__ float Bs[16][64];   // [k][n]
    const int tid = threadIdx.x;
    const int tn = tid & 15;       // cols tn*4 .. +3
    const int tm = tid >> 4;       // rows tm*8 .. +7 (as 4 packed pairs)
    const int m0 = blockIdx.y * 64, n0 = blockIdx.x * 64;

    unsigned long long acc[4][4];
    #pragma unroll
    for (int i = 0; i < 4; i++)
        #pragma unroll
        for (int j = 0; j < 4; j++) acc[i][j] = 0ULL;

    for (int k0 = 0; k0 < K; k0 += 16) {
        // A tile: thread (ma = tid&63, half = tid>>6) loads A[m0+ma][k0+half*8 ..+7]
        {
            int ma = tid & 63, half = tid >> 6;
            const float* Ar = A + (size_t)(m0 + ma) * K + (k0 + half * 8);
            #pragma unroll
            for (int j = 0; j < 8; j++) {
                int gk = k0 + half * 8 + j;
                As[half * 8 + j][ma] = (gk < K) ? Ar[j] : 0.f;
            }
        }
        // B tile
        if (!TRANSB) {
            int kk = tid >> 3, n8 = (tid & 7) * 8;
            int gk = k0 + kk, gn = n0 + n8;
            const float* Br = Bm + (size_t)gk * Nd + gn;
            #pragma unroll
            for (int j = 0; j < 8; j++)
                Bs[kk][n8 + j] = (gk < K) ? Br[j] : 0.f;
        } else {
            int nb = tid >> 1, k8 = (tid & 1) * 8;
            const float* Br = Bm + (size_t)(n0 + nb) * K + (k0 + k8);
            #pragma unroll
            for (int j = 0; j < 8; j++) {
                int gk = k0 + k8 + j;
                Bs[k8 + j][nb] = (gk < K) ? Br[j] : 0.f;
            }
        }
        __syncthreads();
        #pragma unroll
        for (int k = 0; k < 16; k++) {
            unsigned long long a[4], b[4];
            const unsigned long long* ap =
                (const unsigned long long*)&As[k][tm * 8];
            #pragma unroll
            for (int i = 0; i < 4; i++) a[i] = ap[i];
            float4 bf = *(const float4*)&Bs[k][tn * 4];
            {
                unsigned bx = __float_as_uint(bf.x), by = __float_as_uint(bf.y);
                unsigned bz = __float_as_uint(bf.z), bw = __float_as_uint(bf.w);
                asm("mov.b64 %0, {%1, %1};" : "=l"(b[0]) : "r"(bx));
                asm("mov.b64 %0, {%1, %1};" : "=l"(b[1]) : "r"(by));
                asm("mov.b64 %0, {%1, %1};" : "=l"(b[2]) : "r"(bz));
                asm("mov.b64 %0, {%1, %1};" : "=l"(b[3]) : "r"(bw));
            }
            #pragma unroll
            for (int i = 0; i < 4; i++)
                #pragma unroll
                for (int j = 0; j < 4; j++)
                    asm("fma.rn.f32x2 %0, %1, %2, %0;"
                        : "+l"(acc[i][j]) : "l"(a[i]), "l"(b[j]));
        }
        __syncthreads();
    }
    // epilogue
    #pragma unroll
    for (int i = 0; i < 4; i++) {
        int gm = m0 + tm * 8 + 2 * i;
        float rs0 = rowscale ? rowscale[gm] : 1.f;
        float rs1 = rowscale ? rowscale[gm + 1] : 1.f;
        #pragma unroll
        for (int j = 0; j < 4; j++) {
            int gn = n0 + tn * 4 + j;
            unsigned lo, hi;
            asm("mov.b64 {%0, %1}, %2;" : "=r"(lo), "=r"(hi) : "l"(acc[i][j]));
            float bv = bias ? bias[gn] : 0.f;
            float v0 = __uint_as_float(lo) * rs0 + bv;
            float v1 = __uint_as_float(hi) * rs1 + bv;
            if (ACT == 1) { v0 = fmaxf(v0, 0.f); v1 = fmaxf(v1, 0.f); }
            if (ACT == 2) {
                v0 = (v0 >= 0.f) ? v0 : 0.01f * v0;
                v1 = (v1 >= 0.f) ? v1 : 0.01f * v1;
            }
            C[(size_t)gm * Nd + gn] = v0;
            C[(size_t)(gm + 1) * Nd + gn] = v1;
        }
    }
}

// gconv2 scatter: agg2[dst] += h1[src] * inv_s[src]
__global__ void k_scatter2(const int* __restrict__ src, const int* __restrict__ dst) {
    int t = blockIdx.x * blockDim.x + threadIdx.x;
    if (t >= EE * DD) return;
    int e = t >> 8, j = t & 255;
    int s = src[e], d = dst[e];
    atomicAdd(&g_scratch[OFF_AGG2 + (size_t)d * DD + j],
              g_scratch[OFF_H1 + (size_t)s * DD + j] * g_scratch[OFF_INVS + s]);
}

// NNConv message scatter: macc[dst] += t_e*hM[src] + hC2[src]
__global__ void k_scatter3(const int* __restrict__ src, const int* __restrict__ dst,
                           const float* __restrict__ edge_type) {
    int t = blockIdx.x * blockDim.x + threadIdx.x;
    if (t >= EE * DD) return;
    int e = t >> 8, j = t & 255;
    int s = src[e], d = dst[e];
    float te = edge_type[e];
    const float* row = &g_scratch[OFF_HMC + (size_t)s * 512];
    atomicAdd(&g_scratch[OFF_MACC + (size_t)d * DD + j], te * row[j] + row[256 + j]);
}

__global__ void k_mrelu(const float* __restrict__ b_nn) {
    int t = blockIdx.x * blockDim.x + threadIdx.x;
    if (t >= NN * DD) return;
    int j = t & 255;
    g_scratch[OFF_M + t] = fmaxf(g_scratch[OFF_MACC + t] + b_nn[j], 0.f);
}

__global__ void k_gru() {
    int t = blockIdx.x * blockDim.x + threadIdx.x;
    if (t >= NN * DD) return;
    int row = t >> 8, j = t & 255;
    const float* gi = &g_scratch[OFF_GI + (size_t)row * 768];
    const float* gh = &g_scratch[OFF_GH + (size_t)row * 768];
    float r = 1.f / (1.f + expf(-(gi[j] + gh[j])));
    float z = 1.f / (1.f + expf(-(gi[256 + j] + gh[256 + j])));
    float nv = tanhf(gi[512 + j] + r * gh[512 + j]);
    float hid = g_scratch[OFF_H + t];
    g_scratch[OFF_HN + t] = (1.f - z) * nv + z * hid;
}

__global__ void k_nread(const int* __restrict__ node_gid) {
    int t = blockIdx.x * blockDim.x + threadIdx.x;
    if (t >= NN * DD) return;
    int row = t >> 8, j = t & 255;
    atomicAdd(&g_scratch[OFF_NSUM + (size_t)node_gid[row] * DD + j], g_scratch[OFF_HN + t]);
}

__global__ void k_ghf() {
    int t = blockIdx.x * blockDim.x + threadIdx.x;
    if (t >= BB * 257) return;
    int g = t / 257, j = t - g * 257;
    float v;
    if (j < 256) {
        float nc = (float)max(g_iscratch[IOFF_NCNT + g], 1);
        v = g_scratch[OFF_NSUM + (size_t)g * DD + j] / nc;
    } else {
        float ec = (float)max(g_iscratch[IOFF_ECNT + g], 1);
        v = g_scratch[OFF_ESUM + g] / ec;
    }
    g_scratch[OFF_GHF + t] = v;
}

__device__ __forceinline__ float leaky01(float x) { return (x >= 0.f) ? x : 0.01f * x; }

// fused 3-layer MLP head; one block per graph
__global__ void k_head(const float* __restrict__ Wr0, const float* __restrict__ br0,
                       const float* __restrict__ g0, const float* __restrict__ beta0,
                       const float* __restrict__ Wr1, const float* __restrict__ br1,
                       const float* __restrict__ g1, const float* __restrict__ beta1,
                       const float* __restrict__ Wout, const float* __restrict__ bout,
                       float* __restrict__ out) {
    __shared__ float sx[257];
    __shared__ float sy[256];
    __shared__ float red[256];
    int g = blockIdx.x, t = threadIdx.x;
    sx[t] = g_scratch[OFF_GHF + (size_t)g * 257 + t];
    if (t == 0) sx[256] = g_scratch[OFF_GHF + (size_t)g * 257 + 256];
    __syncthreads();
    float acc = 0.f;
    for (int j = 0; j < 257; j++) acc += sx[j] * Wr0[(size_t)j * 256 + t];
    sy[t] = leaky01((acc + br0[t]) * g0[t] + beta0[t]);
    __syncthreads();
    acc = 0.f;
    for (int j = 0; j < 256; j++) acc += sy[j] * Wr1[(size_t)j * 256 + t];
    float x2 = leaky01((acc + br1[t]) * g1[t] + beta1[t]);
    red[t] = x2 * Wout[t];
    __syncthreads();
    for (int s = 128; s > 0; s >>= 1) {
        if (t < s) red[t] += red[t + s];
        __syncthreads();
    }
    if (t == 0) out[g] = red[0] + bout[0];
}

// ---------------- launch ----------------
extern "C" void kernel_launch(void* const* d_in, const int* in_sizes, int n_in,
                              void* d_out, int out_size) {
    const float* node_feats = (const float*)d_in[0];
    const float* edge_type  = (const float*)d_in[1];
    const int*   src        = (const int*)d_in[2];
    const int*   dst        = (const int*)d_in[3];
    const int*   node_gid   = (const int*)d_in[4];
    const int*   edge_gid   = (const int*)d_in[5];
    int wb = (in_sizes[6] == 1) ? 7 : 6;
    const float* W1   = (const float*)d_in[wb + 0];
    const float* b1   = (const float*)d_in[wb + 1];
    const float* W2   = (const float*)d_in[wb + 2];
    const float* b2   = (const float*)d_in[wb + 3];
    const float* Wp   = (const float*)d_in[wb + 4];
    const float* bp   = (const float*)d_in[wb + 5];
    const float* We1  = (const float*)d_in[wb + 6];
    const float* be1  = (const float*)d_in[wb + 7];
    const float* We2  = (const float*)d_in[wb + 8];
    const float* be2  = (const float*)d_in[wb + 9];
    const float* b_nn = (const float*)d_in[wb + 10];
    const float* W_ih = (const float*)d_in[wb + 11];
    const float* b_ih = (const float*)d_in[wb + 12];
    const float* W_hh = (const float*)d_in[wb + 13];
    const float* b_hh = (const float*)d_in[wb + 14];
    const float* Wr0  = (const float*)d_in[wb + 15];
    const float* br0  = (const float*)d_in[wb + 16];
    const float* g0   = (const float*)d_in[wb + 17];
    const float* beta0= (const float*)d_in[wb + 18];
    const float* Wr1  = (const float*)d_in[wb + 19];
    const float* br1  = (const float*)d_in[wb + 20];
    const float* g1   = (const float*)d_in[wb + 21];
    const float* beta1= (const float*)d_in[wb + 22];
    const float* Wout = (const float*)d_in[wb + 23];
    const float* bout = (const float*)d_in[wb + 24];
    float* out = (float*)d_out;

    float* S = nullptr;
    cudaGetSymbolAddress((void**)&S, g_scratch);

    k_zero<<<(int)((ZERO_F + 255) / 256), 256>>>();
    k_prep<<<(EE + 255) / 256, 256>>>(src, dst, node_gid, edge_gid, edge_type);
    k_finalize<<<(NN + 255) / 256, 256>>>(We1, be1);
    k_scatter1<<<(EE * INF + 255) / 256, 256>>>(node_feats, src, dst);
    k_build_bcat<<<(DD * DD + 255) / 256, 256>>>(We2, be2);
    // h1 = relu(inv_d .* (agg1@W1) + b1)
    {
        dim3 grid(DD / 64, NN / 64);
        k_gemm2<false, 1><<<grid, 128>>>(S + OFF_AGG1, W1, S + OFF_H1, NN, DD, INF, b1, S + OFF_INVD);
    }
    k_scatter2<<<(EE * DD + 255) / 256, 256>>>(src, dst);
    // h2 = relu(inv_d .* (agg2@W2) + b2)
    {
        dim3 grid(DD / 64, NN / 64);
        k_gemm2<false, 1><<<grid, 128>>>(S + OFF_AGG2, W2, S + OFF_H2, NN, DD, DD, b2, S + OFF_INVD);
    }
    // h = leaky(h2@Wp + bp)
    {
        dim3 grid(DD / 64, NN / 64);
        k_gemm2<false, 2><<<grid, 128>>>(S + OFF_H2, Wp, S + OFF_H, NN, DD, DD, bp, nullptr);
    }
    // hmc = h @ Bcat -> [hM | hC2]
    {
        dim3 grid(512 / 64, NN / 64);
        k_gemm2<false, 0><<<grid, 128>>>(S + OFF_H, S + OFF_BCAT, S + OFF_HMC, NN, 512, DD, nullptr, nullptr);
    }
    k_scatter3<<<(EE * DD + 255) / 256, 256>>>(src, dst, edge_type);
    k_mrelu<<<(NN * DD + 255) / 256, 256>>>(b_nn);
    // GRU gates
    {
        dim3 grid(768 / 64, NN / 64);
        k_gemm2<true, 0><<<grid, 128>>>(S + OFF_M, W_ih, S + OFF_GI, NN, 768, DD, b_ih, nullptr);
        k_gemm2<true, 0><<<grid, 128>>>(S + OFF_H, W_hh, S + OFF_GH, NN, 768, DD, b_hh, nullptr);
    }
    k_gru<<<(NN * DD + 255) / 256, 256>>>();
    k_nread<<<(NN * DD + 255) / 256, 256>>>(node_gid);
    k_ghf<<<(BB * 257 + 255) / 256, 256>>>();
    k_head<<<BB, 256>>>(Wr0, br0, g0, beta0, Wr1, br1, g1, beta1, Wout, bout, out);
}

// round 3
// speedup vs baseline: 1.0742x; 1.0742x over previous
#include <cuda_runtime.h>
#include <math.h>
#include <stdint.h>

// Problem constants (fixed by the benchmark)
#define NN   4096   // nodes
#define EE   4096   // edges
#define BB   128    // graphs
#define DD   256    // hidden dim
#define INF  74     // input feature dim
#define EHH  512    // edge-net hidden

// ---------------- scratch (static device globals; no allocation) ----------------
#define OFF_AGG1  0ULL                                  // NN*INF
#define OFF_AGG2  (OFF_AGG1 + (size_t)NN*INF)           // NN*DD
#define OFF_MACC  (OFF_AGG2 + (size_t)NN*DD)            // NN*DD
#define OFF_NSUM  (OFF_MACC + (size_t)NN*DD)            // BB*DD
#define OFF_ESUM  (OFF_NSUM + (size_t)BB*DD)            // BB
#define ZERO_F    (OFF_ESUM + (size_t)BB)

#define OFF_INVS  ZERO_F                                // NN
#define OFF_INVD  (OFF_INVS + (size_t)NN)               // NN
#define OFF_U     (OFF_INVD + (size_t)NN)               // EHH
#define OFF_W     (OFF_U + (size_t)EHH)                 // EHH
#define OFF_BCAT  (OFF_W + (size_t)EHH)                 // DD*512
#define OFF_H1    (OFF_BCAT + (size_t)DD*512)           // NN*DD
#define OFF_H2    (OFF_H1 + (size_t)NN*DD)              // NN*DD
#define OFF_H     (OFF_H2 + (size_t)NN*DD)              // NN*DD
#define OFF_HMC   (OFF_H + (size_t)NN*DD)               // NN*512
#define OFF_M     (OFF_HMC + (size_t)NN*512)            // NN*DD
#define OFF_GI    (OFF_M + (size_t)NN*DD)               // NN*768
#define OFF_GH    (OFF_GI + (size_t)NN*768)             // NN*768
#define OFF_HN    (OFF_GH + (size_t)NN*768)             // NN*DD
#define OFF_GHF   (OFF_HN + (size_t)NN*DD)              // BB*257
#define TOT_F     (OFF_GHF + (size_t)BB*257)

__device__ float g_scratch[TOT_F];

#define IOFF_DEGOUT 0
#define IOFF_DEGIN  NN
#define IOFF_NCNT   (2*NN)
#define IOFF_ECNT   (2*NN + BB)
#define TOT_I       (2*NN + 2*BB)
__device__ int g_iscratch[TOT_I];

// ---------------- small kernels (unchanged from the 359us version) -------------

__global__ void k_zero() {
    size_t i = (size_t)blockIdx.x * blockDim.x + threadIdx.x;
    if (i < ZERO_F) g_scratch[i] = 0.f;
    if (i < TOT_I) g_iscratch[i] = 0;
}

__global__ void k_prep(const int* __restrict__ src, const int* __restrict__ dst,
                       const int* __restrict__ node_gid, const int* __restrict__ edge_gid,
                       const float* __restrict__ edge_type) {
    int i = blockIdx.x * blockDim.x + threadIdx.x;
    if (i < EE) {
        atomicAdd(&g_iscratch[IOFF_DEGOUT + src[i]], 1);
        atomicAdd(&g_iscratch[IOFF_DEGIN + dst[i]], 1);
        atomicAdd(&g_iscratch[IOFF_ECNT + edge_gid[i]], 1);
        atomicAdd(&g_scratch[OFF_ESUM + edge_gid[i]], edge_type[i]);
    }
    if (i < NN) {
        atomicAdd(&g_iscratch[IOFF_NCNT + node_gid[i]], 1);
    }
}

__global__ void k_finalize(const float* __restrict__ We1, const float* __restrict__ be1) {
    int i = blockIdx.x * blockDim.x + threadIdx.x;
    if (i < NN) {
        float od = (float)max(g_iscratch[IOFF_DEGOUT + i], 1);
        float id = (float)max(g_iscratch[IOFF_DEGIN + i], 1);
        g_scratch[OFF_INVS + i] = rsqrtf(od);
        g_scratch[OFF_INVD + i] = rsqrtf(id);
    }
    if (i < EHH) {
        float a = We1[i], b = be1[i];
        float s = (a * 0.5f + b >= 0.f) ? 1.f : 0.01f;
        g_scratch[OFF_U + i] = s * a;
        g_scratch[OFF_W + i] = s * b;
    }
}

__global__ void k_scatter1(const float* __restrict__ x, const int* __restrict__ src,
                           const int* __restrict__ dst) {
    int t = blockIdx.x * blockDim.x + threadIdx.x;
    if (t >= EE * INF) return;
    int e = t / INF, j = t - e * INF;
    int s = src[e], d = dst[e];
    atomicAdd(&g_scratch[OFF_AGG1 + (size_t)d * INF + j],
              x[(size_t)s * INF + j] * g_scratch[OFF_INVS + s]);
}

// Build Bcat[d][0:256]=M and Bcat[d][256:512]=C2 (streams We2 once)
__global__ void k_build_bcat(const float* __restrict__ We2, const float* __restrict__ be2) {
    __shared__ float su_s[EHH], sw_s[EHH];
    for (int i = threadIdx.x; i < EHH; i += blockDim.x) {
        su_s[i] = g_scratch[OFF_U + i];
        sw_s[i] = g_scratch[OFF_W + i];
    }
    __syncthreads();
    int j = blockIdx.x * blockDim.x + threadIdx.x;
    if (j >= DD * DD) return;
    float su = 0.f, sw = 0.f;
    #pragma unroll 8
    for (int k = 0; k < EHH; k++) {
        float v = We2[(size_t)k * (DD * DD) + j];
        su += su_s[k] * v;
        sw += sw_s[k] * v;
    }
    int d = j >> 8, f = j & 255;
    g_scratch[OFF_BCAT + (size_t)d * 512 + f] = su;
    g_scratch[OFF_BCAT + (size_t)d * 512 + 256 + f] = sw + be2[j];
}

// -------- TF32 tensor-core GEMM: C = act(rowscale[m]*(A@B) + bias[n]) --------
// Tile 64x64x16, 128 threads = 4 warps (2x2), each warp computes 32x32 via
// 8x mma.sync.m16n8k8 tf32 per k8 step. Inputs converted to tf32 at smem store.
// A: [M,K] row-major. B: [K,N] (TRANSB=false) or [N,K] (TRANSB=true), row-major.
template<bool TRANSB, int ACT>  // ACT: 0 none, 1 relu, 2 leaky(0.01)
__global__ void __launch_bounds__(128)
k_gemm_tf32(const float* __restrict__ A, const float* __restrict__ Bm,
            float* __restrict__ C, int M, int Nd, int K,
            const float* __restrict__ bias, const float* __restrict__ rowscale) {
    __shared__ uint32_t As[16][68];   // [k][m], tf32 bits, pad 4
    __shared__ uint32_t Bs[16][68];   // [k][n]
    const int tid = threadIdx.x;
    const int wid = tid >> 5, lane = tid & 31;
    const int g = lane >> 2, tg = lane & 3;     // groupID, threadID_in_group
    const int mw = (wid >> 1) * 32;             // warp M offset in tile
    const int nw = (wid & 1) * 32;              // warp N offset in tile
    const int m0 = blockIdx.y * 64, n0 = blockIdx.x * 64;

    float acc[2][4][4];
    #pragma unroll
    for (int mi = 0; mi < 2; mi++)
        #pragma unroll
        for (int nj = 0; nj < 4; nj++)
            #pragma unroll
            for (int r = 0; r < 4; r++) acc[mi][nj][r] = 0.f;

    for (int k0 = 0; k0 < K; k0 += 16) {
        // A tile: thread (ma = tid&63, half = tid>>6) loads A[m0+ma][k0+half*8..+7]
        {
            int ma = tid & 63, half = tid >> 6;
            const float* Ar = A + (size_t)(m0 + ma) * K + (k0 + half * 8);
            #pragma unroll
            for (int j = 0; j < 8; j++) {
                int gk = k0 + half * 8 + j;
                float v = (gk < K) ? Ar[j] : 0.f;
                uint32_t t32;
                asm("cvt.rna.tf32.f32 %0, %1;" : "=r"(t32) : "f"(v));
                As[half * 8 + j][ma] = t32;
            }
        }
        // B tile
        if (!TRANSB) {
            int kk = tid >> 3, nb = (tid & 7) * 8;
            int gk = k0 + kk;
            const float* Br = Bm + (size_t)gk * Nd + (n0 + nb);
            #pragma unroll
            for (int j = 0; j < 8; j++) {
                float v = (gk < K) ? Br[j] : 0.f;
                uint32_t t32;
                asm("cvt.rna.tf32.f32 %0, %1;" : "=r"(t32) : "f"(v));
                Bs[kk][nb + j] = t32;
            }
        } else {
            int nb = tid >> 1, k8 = (tid & 1) * 8;
            const float* Br = Bm + (size_t)(n0 + nb) * K + (k0 + k8);
            #pragma unroll
            for (int j = 0; j < 8; j++) {
                int gk = k0 + k8 + j;
                float v = (gk < K) ? Br[j] : 0.f;
                uint32_t t32;
                asm("cvt.rna.tf32.f32 %0, %1;" : "=r"(t32) : "f"(v));
                Bs[k8 + j][nb] = t32;
            }
        }
        __syncthreads();
        #pragma unroll
        for (int ks = 0; ks < 2; ks++) {
            const int kb = ks * 8;
            uint32_t a[2][4], b[4][2];
            #pragma unroll
            for (int mi = 0; mi < 2; mi++) {
                int mr = mw + mi * 16;
                a[mi][0] = As[kb + tg][mr + g];
                a[mi][1] = As[kb + tg][mr + g + 8];
                a[mi][2] = As[kb + tg + 4][mr + g];
                a[mi][3] = As[kb + tg + 4][mr + g + 8];
            }
            #pragma unroll
            for (int nj = 0; nj < 4; nj++) {
                int nc = nw + nj * 8;
                b[nj][0] = Bs[kb + tg][nc + g];
                b[nj][1] = Bs[kb + tg + 4][nc + g];
            }
            #pragma unroll
            for (int mi = 0; mi < 2; mi++)
                #pragma unroll
                for (int nj = 0; nj < 4; nj++)
                    asm volatile(
                        "mma.sync.aligned.m16n8k8.row.col.f32.tf32.tf32.f32 "
                        "{%0,%1,%2,%3}, {%4,%5,%6,%7}, {%8,%9}, {%0,%1,%2,%3};"
                        : "+f"(acc[mi][nj][0]), "+f"(acc[mi][nj][1]),
                          "+f"(acc[mi][nj][2]), "+f"(acc[mi][nj][3])
                        : "r"(a[mi][0]), "r"(a[mi][1]), "r"(a[mi][2]), "r"(a[mi][3]),
                          "r"(b[nj][0]), "r"(b[nj][1]));
        }
        __syncthreads();
    }
    // epilogue: c0=(g, 2tg), c1=(g, 2tg+1), c2=(g+8, 2tg), c3=(g+8, 2tg+1)
    #pragma unroll
    for (int mi = 0; mi < 2; mi++) {
        #pragma unroll
        for (int r = 0; r < 2; r++) {
            int gm = m0 + mw + mi * 16 + g + r * 8;
            float rs = rowscale ? rowscale[gm] : 1.f;
            #pragma unroll
            for (int nj = 0; nj < 4; nj++) {
                int gn = n0 + nw + nj * 8 + 2 * tg;
                float bv0 = bias ? bias[gn] : 0.f;
                float bv1 = bias ? bias[gn + 1] : 0.f;
                float v0 = acc[mi][nj][r * 2 + 0] * rs + bv0;
                float v1 = acc[mi][nj][r * 2 + 1] * rs + bv1;
                if (ACT == 1) { v0 = fmaxf(v0, 0.f); v1 = fmaxf(v1, 0.f); }
                if (ACT == 2) {
                    v0 = (v0 >= 0.f) ? v0 : 0.01f * v0;
                    v1 = (v1 >= 0.f) ? v1 : 0.01f * v1;
                }
                C[(size_t)gm * Nd + gn] = v0;
                C[(size_t)gm * Nd + gn + 1] = v1;
            }
        }
    }
}

// gconv2 scatter: agg2[dst] += h1[src] * inv_s[src]
__global__ void k_scatter2(const int* __restrict__ src, const int* __restrict__ dst) {
    int t = blockIdx.x * blockDim.x + threadIdx.x;
    if (t >= EE * DD) return;
    int e = t >> 8, j = t & 255;
    int s = src[e], d = dst[e];
    atomicAdd(&g_scratch[OFF_AGG2 + (size_t)d * DD + j],
              g_scratch[OFF_H1 + (size_t)s * DD + j] * g_scratch[OFF_INVS + s]);
}

// NNConv message scatter: macc[dst] += t_e*hM[src] + hC2[src]
__global__ void k_scatter3(const int* __restrict__ src, const int* __restrict__ dst,
                           const float* __restrict__ edge_type) {
    int t = blockIdx.x * blockDim.x + threadIdx.x;
    if (t >= EE * DD) return;
    int e = t >> 8, j = t & 255;
    int s = src[e], d = dst[e];
    float te = edge_type[e];
    const float* row = &g_scratch[OFF_HMC + (size_t)s * 512];
    atomicAdd(&g_scratch[OFF_MACC + (size_t)d * DD + j], te * row[j] + row[256 + j]);
}

__global__ void k_mrelu(const float* __restrict__ b_nn) {
    int t = blockIdx.x * blockDim.x + threadIdx.x;
    if (t >= NN * DD) return;
    int j = t & 255;
    g_scratch[OFF_M + t] = fmaxf(g_scratch[OFF_MACC + t] + b_nn[j], 0.f);
}

__global__ void k_gru() {
    int t = blockIdx.x * blockDim.x + threadIdx.x;
    if (t >= NN * DD) return;
    int row = t >> 8, j = t & 255;
    const float* gi = &g_scratch[OFF_GI + (size_t)row * 768];
    const float* gh = &g_scratch[OFF_GH + (size_t)row * 768];
    float r = 1.f / (1.f + expf(-(gi[j] + gh[j])));
    float z = 1.f / (1.f + expf(-(gi[256 + j] + gh[256 + j])));
    float nv = tanhf(gi[512 + j] + r * gh[512 + j]);
    float hid = g_scratch[OFF_H + t];
    g_scratch[OFF_HN + t] = (1.f - z) * nv + z * hid;
}

__global__ void k_nread(const int* __restrict__ node_gid) {
    int t = blockIdx.x * blockDim.x + threadIdx.x;
    if (t >= NN * DD) return;
    int row = t >> 8, j = t & 255;
    atomicAdd(&g_scratch[OFF_NSUM + (size_t)node_gid[row] * DD + j], g_scratch[OFF_HN + t]);
}

__global__ void k_ghf() {
    int t = blockIdx.x * blockDim.x + threadIdx.x;
    if (t >= BB * 257) return;
    int g = t / 257, j = t - g * 257;
    float v;
    if (j < 256) {
        float nc = (float)max(g_iscratch[IOFF_NCNT + g], 1);
        v = g_scratch[OFF_NSUM + (size_t)g * DD + j] / nc;
    } else {
        float ec = (float)max(g_iscratch[IOFF_ECNT + g], 1);
        v = g_scratch[OFF_ESUM + g] / ec;
    }
    g_scratch[OFF_GHF + t] = v;
}

__device__ __forceinline__ float leaky01(float x) { return (x >= 0.f) ? x : 0.01f * x; }

// fused 3-layer MLP head; one block per graph
__global__ void k_head(const float* __restrict__ Wr0, const float* __restrict__ br0,
                       const float* __restrict__ g0, const float* __restrict__ beta0,
                       const float* __restrict__ Wr1, const float* __restrict__ br1,
                       const float* __restrict__ g1, const float* __restrict__ beta1,
                       const float* __restrict__ Wout, const float* __restrict__ bout,
                       float* __restrict__ out) {
    __shared__ float sx[257];
    __shared__ float sy[256];
    __shared__ float red[256];
    int g = blockIdx.x, t = threadIdx.x;
    sx[t] = g_scratch[OFF_GHF + (size_t)g * 257 + t];
    if (t == 0) sx[256] = g_scratch[OFF_GHF + (size_t)g * 257 + 256];
    __syncthreads();
    float acc = 0.f;
    for (int j = 0; j < 257; j++) acc += sx[j] * Wr0[(size_t)j * 256 + t];
    sy[t] = leaky01((acc + br0[t]) * g0[t] + beta0[t]);
    __syncthreads();
    acc = 0.f;
    for (int j = 0; j < 256; j++) acc += sy[j] * Wr1[(size_t)j * 256 + t];
    float x2 = leaky01((acc + br1[t]) * g1[t] + beta1[t]);
    red[t] = x2 * Wout[t];
    __syncthreads();
    for (int s = 128; s > 0; s >>= 1) {
        if (t < s) red[t] += red[t + s];
        __syncthreads();
    }
    if (t == 0) out[g] = red[0] + bout[0];
}

// ---------------- launch ----------------
extern "C" void kernel_launch(void* const* d_in, const int* in_sizes, int n_in,
                              void* d_out, int out_size) {
    const float* node_feats = (const float*)d_in[0];
    const float* edge_type  = (const float*)d_in[1];
    const int*   src        = (const int*)d_in[2];
    const int*   dst        = (const int*)d_in[3];
    const int*   node_gid   = (const int*)d_in[4];
    const int*   edge_gid   = (const int*)d_in[5];
    int wb = (in_sizes[6] == 1) ? 7 : 6;
    const float* W1   = (const float*)d_in[wb + 0];
    const float* b1   = (const float*)d_in[wb + 1];
    const float* W2   = (const float*)d_in[wb + 2];
    const float* b2   = (const float*)d_in[wb + 3];
    const float* Wp   = (const float*)d_in[wb + 4];
    const float* bp   = (const float*)d_in[wb + 5];
    const float* We1  = (const float*)d_in[wb + 6];
    const float* be1  = (const float*)d_in[wb + 7];
    const float* We2  = (const float*)d_in[wb + 8];
    const float* be2  = (const float*)d_in[wb + 9];
    const float* b_nn = (const float*)d_in[wb + 10];
    const float* W_ih = (const float*)d_in[wb + 11];
    const float* b_ih = (const float*)d_in[wb + 12];
    const float* W_hh = (const float*)d_in[wb + 13];
    const float* b_hh = (const float*)d_in[wb + 14];
    const float* Wr0  = (const float*)d_in[wb + 15];
    const float* br0  = (const float*)d_in[wb + 16];
    const float* g0   = (const float*)d_in[wb + 17];
    const float* beta0= (const float*)d_in[wb + 18];
    const float* Wr1  = (const float*)d_in[wb + 19];
    const float* br1  = (const float*)d_in[wb + 20];
    const float* g1   = (const float*)d_in[wb + 21];
    const float* beta1= (const float*)d_in[wb + 22];
    const float* Wout = (const float*)d_in[wb + 23];
    const float* bout = (const float*)d_in[wb + 24];
    float* out = (float*)d_out;

    float* S = nullptr;
    cudaGetSymbolAddress((void**)&S, g_scratch);

    k_zero<<<(int)((ZERO_F + 255) / 256), 256>>>();
    k_prep<<<(EE + 255) / 256, 256>>>(src, dst, node_gid, edge_gid, edge_type);
    k_finalize<<<(NN + 255) / 256, 256>>>(We1, be1);
    k_scatter1<<<(EE * INF + 255) / 256, 256>>>(node_feats, src, dst);
    k_build_bcat<<<(DD * DD + 255) / 256, 256>>>(We2, be2);
    // h1 = relu(inv_d .* (agg1@W1) + b1)
    {
        dim3 grid(DD / 64, NN / 64);
        k_gemm_tf32<false, 1><<<grid, 128>>>(S + OFF_AGG1, W1, S + OFF_H1, NN, DD, INF, b1, S + OFF_INVD);
    }
    k_scatter2<<<(EE * DD + 255) / 256, 256>>>(src, dst);
    // h2 = relu(inv_d .* (agg2@W2) + b2)
    {
        dim3 grid(DD / 64, NN / 64);
        k_gemm_tf32<false, 1><<<grid, 128>>>(S + OFF_AGG2, W2, S + OFF_H2, NN, DD, DD, b2, S + OFF_INVD);
    }
    // h = leaky(h2@Wp + bp)
    {
        dim3 grid(DD / 64, NN / 64);
        k_gemm_tf32<false, 2><<<grid, 128>>>(S + OFF_H2, Wp, S + OFF_H, NN, DD, DD, bp, nullptr);
    }
    // hmc = h @ Bcat -> [hM | hC2]
    {
        dim3 grid(512 / 64, NN / 64);
        k_gemm_tf32<false, 0><<<grid, 128>>>(S + OFF_H, S + OFF_BCAT, S + OFF_HMC, NN, 512, DD, nullptr, nullptr);
    }
    k_scatter3<<<(EE * DD + 255) / 256, 256>>>(src, dst, edge_type);
    k_mrelu<<<(NN * DD + 255) / 256, 256>>>(b_nn);
    // GRU gates
    {
        dim3 grid(768 / 64, NN / 64);
        k_gemm_tf32<true, 0><<<grid, 128>>>(S + OFF_M, W_ih, S + OFF_GI, NN, 768, DD, b_ih, nullptr);
        k_gemm_tf32<true, 0><<<grid, 128>>>(S + OFF_H, W_hh, S + OFF_GH, NN, 768, DD, b_hh, nullptr);
    }
    k_gru<<<(NN * DD + 255) / 256, 256>>>();
    k_nread<<<(NN * DD + 255) / 256, 256>>>(node_gid);
    k_ghf<<<(BB * 257 + 255) / 256, 256>>>();
    k_head<<<BB, 256>>>(Wr0, br0, g0, beta0, Wr1, br1, g1, beta1, Wout, bout, out);
}